// round 2
// baseline (speedup 1.0000x reference)
#include <cuda_runtime.h>
#include <cuda_bf16.h>

// Problem sizes (fixed by the dataset): 1,000,000 nodes, 2,000,000 elements.
#define MAX_NODES 1000000

// Scratch: device globals (allocation-free per harness rules).
__device__ float  g_uphys[3 * MAX_NODES];
__device__ float  g_fint [3 * MAX_NODES];
__device__ double g_sums[2];     // [0] = sum(R_free^2), [1] = sum(F_free^2)
__device__ int    g_conn_is64;   // 1 if connectivity is int64, 0 if int32

// -------- Kernel 0: probe connectivity dtype --------------------------------
// If int64 (little-endian, indices < 1e6): every odd 32-bit word is 0.
// If int32: odd words are random node indices (virtually all nonzero).
__global__ void detect_conn_kernel(const unsigned int* __restrict__ conn_w,
                                   int n_words)
{
    __shared__ unsigned int acc;
    if (threadIdx.x == 0) acc = 0u;
    __syncthreads();
    unsigned int v = 0u;
    // sample odd words among the first 8192 words (or fewer)
    int lim = n_words < 8192 ? n_words : 8192;
    for (int i = 2 * threadIdx.x + 1; i < lim; i += 2 * blockDim.x)
        v |= conn_w[i];
    atomicOr(&acc, v);
    __syncthreads();
    if (threadIdx.x == 0) g_conn_is64 = (acc == 0u) ? 1 : 0;
}

// -------- Kernel 1: u_phys = pred_raw * scale ; F_int = 0 ; zero sums -------
__global__ void prep_kernel(const float* __restrict__ pred_raw,
                            const float* __restrict__ u_c,
                            const float* __restrict__ theta_c,
                            int n3)  // n3 = 3 * n_nodes
{
    if (blockIdx.x == 0 && threadIdx.x == 0) {
        g_sums[0] = 0.0;
        g_sums[1] = 0.0;
    }
    float uc = u_c[0];
    float tc = theta_c[0];
    int stride = gridDim.x * blockDim.x;
    for (int j = blockIdx.x * blockDim.x + threadIdx.x; j < n3; j += stride) {
        int col = j % 3;
        float sc = (col == 2) ? tc : uc;
        g_uphys[j] = pred_raw[j] * sc;
        g_fint[j]  = 0.0f;
    }
}

// -------- Kernel 2: per-element local stiffness force + scatter-add ---------
__global__ void elem_kernel(const void* __restrict__ conn_raw,
                            const float* __restrict__ L,
                            const float* __restrict__ E,
                            const float* __restrict__ A,
                            const float* __restrict__ I22,
                            const float* __restrict__ dirs,       // (E,3)
                            int n_elem, int n_nodes)
{
    int e = blockIdx.x * blockDim.x + threadIdx.x;
    if (e >= n_elem) return;

    long long nA, nB;
    if (g_conn_is64) {
        const long long* conn = (const long long*)conn_raw;
        longlong2 nn = reinterpret_cast<const longlong2*>(conn)[e];
        nA = nn.x; nB = nn.y;
    } else {
        const int* conn = (const int*)conn_raw;
        int2 nn = reinterpret_cast<const int2*>(conn)[e];
        nA = nn.x; nB = nn.y;
    }
    // safety clamp (never triggers on valid data; prevents illegal access)
    if ((unsigned long long)nA >= (unsigned long long)n_nodes) nA = 0;
    if ((unsigned long long)nB >= (unsigned long long)n_nodes) nB = 0;

    float c = dirs[3 * e + 0];
    float s = dirs[3 * e + 2];

    float l    = L[e];
    float Ee   = E[e];
    float EA   = Ee * A[e];
    float EI   = Ee * I22[e];
    float inv_l = 1.0f / l;
    float ea_l  = EA * inv_l;
    float ei_l  = EI * inv_l;
    float ei_l2 = ei_l * inv_l;
    float ei_l3 = ei_l2 * inv_l;

    const float* uA = &g_uphys[3 * nA];
    const float* uB = &g_uphys[3 * nB];
    float uAx = uA[0], uAy = uA[1], uAz = uA[2];
    float uBx = uB[0], uBy = uB[1], uBz = uB[2];

    // local displacement vector
    float d0 =  c * uAx + s * uAy;
    float d1 = -s * uAx + c * uAy;
    float d2 = -uAz;
    float d3 =  c * uBx + s * uBy;
    float d4 = -s * uBx + c * uBy;
    float d5 = -uBz;

    // K_loc @ d_local (axial/bending block structure)
    float du = d0 - d3;
    float dw = d1 - d4;
    float f0 = ea_l * du;
    float f1 = 12.0f * ei_l3 * dw + 6.0f * ei_l2 * (d2 + d5);
    float f2 =  6.0f * ei_l2 * dw + ei_l * (4.0f * d2 + 2.0f * d5);
    float f5 =  6.0f * ei_l2 * dw + ei_l * (2.0f * d2 + 4.0f * d5);
    float f3 = -f0;
    float f4 = -f1;

    // rotate back to global frame and scatter
    atomicAdd(&g_fint[3 * nA + 0],  c * f0 - s * f1);
    atomicAdd(&g_fint[3 * nA + 1],  s * f0 + c * f1);
    atomicAdd(&g_fint[3 * nA + 2], -f2);
    atomicAdd(&g_fint[3 * nB + 0],  c * f3 - s * f4);
    atomicAdd(&g_fint[3 * nB + 1],  s * f3 + c * f4);
    atomicAdd(&g_fint[3 * nB + 2], -f5);
}

// -------- Kernel 3: masked residual sums (double accumulation) --------------
__global__ void reduce_kernel(const float* __restrict__ F_ext,
                              const int*   __restrict__ bc_disp,
                              const int*   __restrict__ bc_rot,
                              int n_nodes)
{
    double sR = 0.0, sF = 0.0;
    int stride = gridDim.x * blockDim.x;
    for (int i = blockIdx.x * blockDim.x + threadIdx.x; i < n_nodes; i += stride) {
        float fd = 1.0f - (float)bc_disp[i];
        float fr = 1.0f - (float)bc_rot[i];
        float fx = F_ext[3 * i + 0];
        float fy = F_ext[3 * i + 1];
        float fz = F_ext[3 * i + 2];
        float rx = (g_fint[3 * i + 0] - fx) * fd;
        float ry = (g_fint[3 * i + 1] - fy) * fd;
        float rz = (g_fint[3 * i + 2] - fz) * fr;
        float gx = fx * fd, gy = fy * fd, gz = fz * fr;
        sR += (double)(rx * rx) + (double)(ry * ry) + (double)(rz * rz);
        sF += (double)(gx * gx) + (double)(gy * gy) + (double)(gz * gz);
    }

    for (int off = 16; off > 0; off >>= 1) {
        sR += __shfl_down_sync(0xFFFFFFFFu, sR, off);
        sF += __shfl_down_sync(0xFFFFFFFFu, sF, off);
    }
    __shared__ double shR[8], shF[8];
    int lane = threadIdx.x & 31;
    int wid  = threadIdx.x >> 5;
    if (lane == 0) { shR[wid] = sR; shF[wid] = sF; }
    __syncthreads();
    if (wid == 0) {
        int nw = (blockDim.x + 31) >> 5;
        sR = (lane < nw) ? shR[lane] : 0.0;
        sF = (lane < nw) ? shF[lane] : 0.0;
        for (int off = 4; off > 0; off >>= 1) {
            sR += __shfl_down_sync(0xFFFFFFFFu, sR, off);
            sF += __shfl_down_sync(0xFFFFFFFFu, sF, off);
        }
        if (lane == 0) {
            atomicAdd(&g_sums[0], sR);
            atomicAdd(&g_sums[1], sF);
        }
    }
}

// -------- Kernel 4: final division ------------------------------------------
__global__ void finalize_kernel(float* __restrict__ out)
{
    double denom = g_sums[1];
    if (denom < 1e-30) denom = 1e-30;
    out[0] = (float)(g_sums[0] / denom);
}

extern "C" void kernel_launch(void* const* d_in, const int* in_sizes, int n_in,
                              void* d_out, int out_size)
{
    const float* pred_raw = (const float*)d_in[0];   // (N,3)
    const float* u_c      = (const float*)d_in[1];   // (1,)
    const float* theta_c  = (const float*)d_in[2];   // (1,)
    const void*  conn     =                d_in[3];  // (E,2) int32 or int64
    const float* L        = (const float*)d_in[4];   // (E,)
    const float* E        = (const float*)d_in[5];
    const float* A        = (const float*)d_in[6];
    const float* I22      = (const float*)d_in[7];
    const float* dirs     = (const float*)d_in[8];   // (E,3)
    const float* F_ext    = (const float*)d_in[9];   // (N,3)
    const int*   bc_disp  = (const int*)  d_in[10];  // (N,1)
    const int*   bc_rot   = (const int*)  d_in[11];  // (N,1)
    float*       out      = (float*)d_out;

    int n_nodes = in_sizes[0] / 3;
    int n_elem  = in_sizes[4];
    int n3      = 3 * n_nodes;

    const int T = 256;
    detect_conn_kernel<<<1, 256>>>((const unsigned int*)conn, 2 * n_elem);
    prep_kernel<<<(n3 + T - 1) / T, T>>>(pred_raw, u_c, theta_c, n3);
    elem_kernel<<<(n_elem + T - 1) / T, T>>>(conn, L, E, A, I22, dirs, n_elem, n_nodes);
    reduce_kernel<<<(n_nodes + T - 1) / T, T>>>(F_ext, bc_disp, bc_rot, n_nodes);
    finalize_kernel<<<1, 1>>>(out);
}

// round 3
// speedup vs baseline: 1.7672x; 1.7672x over previous
#include <cuda_runtime.h>
#include <cuda_bf16.h>

// Problem sizes (fixed by the dataset): 1,000,000 nodes, 2,000,000 elements.
#define MAX_NODES 1000000

// Scratch (device globals; allocation-free). Node arrays padded to 4 floats
// so gathers are single LDG.128 and scatters are single red.global.add.v4.f32.
__device__ float  g_uphys4[4 * MAX_NODES];
__device__ float  g_fint4 [4 * MAX_NODES];
__device__ double g_sums[2];     // [0] = sum(R_free^2), [1] = sum(F_free^2)
__device__ int    g_conn_is64;   // 1 if connectivity is int64, 0 if int32

__device__ __forceinline__ void red_add_v4(float* addr, float x, float y, float z, float w)
{
    asm volatile("red.global.add.v4.f32 [%0], {%1, %2, %3, %4};"
                 :: "l"(addr), "f"(x), "f"(y), "f"(z), "f"(w) : "memory");
}

// -------- Kernel 0: probe connectivity dtype --------------------------------
// int64 little-endian with indices < 1e6  => every odd 32-bit word is 0.
// int32 => odd words are random node indices (virtually all nonzero).
__global__ void detect_conn_kernel(const unsigned int* __restrict__ conn_w,
                                   int n_words)
{
    __shared__ unsigned int acc;
    if (threadIdx.x == 0) acc = 0u;
    __syncthreads();
    unsigned int v = 0u;
    int lim = n_words < 8192 ? n_words : 8192;
    for (int i = 2 * threadIdx.x + 1; i < lim; i += 2 * blockDim.x)
        v |= conn_w[i];
    atomicOr(&acc, v);
    __syncthreads();
    if (threadIdx.x == 0) g_conn_is64 = (acc == 0u) ? 1 : 0;
}

// -------- Kernel 1: u_phys4 = pred_raw * scale (padded) ; F_int4 = 0 --------
__global__ void prep_kernel(const float* __restrict__ pred_raw,
                            const float* __restrict__ u_c,
                            const float* __restrict__ theta_c,
                            int n_nodes)
{
    if (blockIdx.x == 0 && threadIdx.x == 0) {
        g_sums[0] = 0.0;
        g_sums[1] = 0.0;
    }
    float uc = u_c[0];
    float tc = theta_c[0];
    int i = blockIdx.x * blockDim.x + threadIdx.x;
    if (i >= n_nodes) return;
    float px = pred_raw[3 * i + 0];
    float py = pred_raw[3 * i + 1];
    float pz = pred_raw[3 * i + 2];
    reinterpret_cast<float4*>(g_uphys4)[i] = make_float4(px * uc, py * uc, pz * tc, 0.0f);
    reinterpret_cast<float4*>(g_fint4 )[i] = make_float4(0.0f, 0.0f, 0.0f, 0.0f);
}

// -------- Kernel 2: per-element local stiffness force + vector scatter ------
__global__ void elem_kernel(const void* __restrict__ conn_raw,
                            const float* __restrict__ L,
                            const float* __restrict__ E,
                            const float* __restrict__ A,
                            const float* __restrict__ I22,
                            const float* __restrict__ dirs,       // (E,3)
                            int n_elem, int n_nodes)
{
    int e = blockIdx.x * blockDim.x + threadIdx.x;
    if (e >= n_elem) return;

    long long nA, nB;
    if (g_conn_is64) {
        longlong2 nn = reinterpret_cast<const longlong2*>((const long long*)conn_raw)[e];
        nA = nn.x; nB = nn.y;
    } else {
        int2 nn = reinterpret_cast<const int2*>((const int*)conn_raw)[e];
        nA = nn.x; nB = nn.y;
    }
    // safety clamp (never triggers on valid data)
    if ((unsigned long long)nA >= (unsigned long long)n_nodes) nA = 0;
    if ((unsigned long long)nB >= (unsigned long long)n_nodes) nB = 0;

    float c = dirs[3 * e + 0];
    float s = dirs[3 * e + 2];

    float l     = L[e];
    float Ee    = E[e];
    float EA    = Ee * A[e];
    float EI    = Ee * I22[e];
    float inv_l = 1.0f / l;
    float ea_l  = EA * inv_l;
    float ei_l  = EI * inv_l;
    float ei_l2 = ei_l * inv_l;
    float ei_l3 = ei_l2 * inv_l;

    float4 uA = reinterpret_cast<const float4*>(g_uphys4)[nA];
    float4 uB = reinterpret_cast<const float4*>(g_uphys4)[nB];

    // local displacements
    float d0 =  c * uA.x + s * uA.y;
    float d1 = -s * uA.x + c * uA.y;
    float d2 = -uA.z;
    float d3 =  c * uB.x + s * uB.y;
    float d4 = -s * uB.x + c * uB.y;
    float d5 = -uB.z;

    // K_loc @ d_local (axial/bending block structure)
    float du = d0 - d3;
    float dw = d1 - d4;
    float f0 = ea_l * du;
    float f1 = 12.0f * ei_l3 * dw + 6.0f * ei_l2 * (d2 + d5);
    float f2 =  6.0f * ei_l2 * dw + ei_l * (4.0f * d2 + 2.0f * d5);
    float f5 =  6.0f * ei_l2 * dw + ei_l * (2.0f * d2 + 4.0f * d5);

    // global-frame forces; node B x/y are exact negatives of node A's
    float gAx = c * f0 - s * f1;
    float gAy = s * f0 + c * f1;

    red_add_v4(&g_fint4[4 * nA],  gAx,  gAy, -f2, 0.0f);
    red_add_v4(&g_fint4[4 * nB], -gAx, -gAy, -f5, 0.0f);
}

// -------- Kernel 3: masked residual sums ------------------------------------
// fp32 per-thread accumulation (few terms), double from warp-reduce onward.
__global__ void reduce_kernel(const float* __restrict__ F_ext,
                              const int*   __restrict__ bc_disp,
                              const int*   __restrict__ bc_rot,
                              int n_nodes)
{
    float sRf = 0.0f, sFf = 0.0f;
    int base = (blockIdx.x * blockDim.x + threadIdx.x) * 2;
#pragma unroll
    for (int k = 0; k < 2; k++) {
        int i = base + k;
        if (i < n_nodes) {
            float4 fi = reinterpret_cast<const float4*>(g_fint4)[i];
            float fd = 1.0f - (float)bc_disp[i];
            float fr = 1.0f - (float)bc_rot[i];
            float fx = F_ext[3 * i + 0];
            float fy = F_ext[3 * i + 1];
            float fz = F_ext[3 * i + 2];
            float rx = (fi.x - fx) * fd;
            float ry = (fi.y - fy) * fd;
            float rz = (fi.z - fz) * fr;
            float gx = fx * fd, gy = fy * fd, gz = fz * fr;
            sRf += rx * rx + ry * ry + rz * rz;
            sFf += gx * gx + gy * gy + gz * gz;
        }
    }
    double sR = (double)sRf;
    double sF = (double)sFf;

    for (int off = 16; off > 0; off >>= 1) {
        sR += __shfl_down_sync(0xFFFFFFFFu, sR, off);
        sF += __shfl_down_sync(0xFFFFFFFFu, sF, off);
    }
    __shared__ double shR[8], shF[8];
    int lane = threadIdx.x & 31;
    int wid  = threadIdx.x >> 5;
    if (lane == 0) { shR[wid] = sR; shF[wid] = sF; }
    __syncthreads();
    if (wid == 0) {
        int nw = (blockDim.x + 31) >> 5;
        sR = (lane < nw) ? shR[lane] : 0.0;
        sF = (lane < nw) ? shF[lane] : 0.0;
        for (int off = 4; off > 0; off >>= 1) {
            sR += __shfl_down_sync(0xFFFFFFFFu, sR, off);
            sF += __shfl_down_sync(0xFFFFFFFFu, sF, off);
        }
        if (lane == 0) {
            atomicAdd(&g_sums[0], sR);
            atomicAdd(&g_sums[1], sF);
        }
    }
}

// -------- Kernel 4: final division ------------------------------------------
__global__ void finalize_kernel(float* __restrict__ out)
{
    double denom = g_sums[1];
    if (denom < 1e-30) denom = 1e-30;
    out[0] = (float)(g_sums[0] / denom);
}

extern "C" void kernel_launch(void* const* d_in, const int* in_sizes, int n_in,
                              void* d_out, int out_size)
{
    const float* pred_raw = (const float*)d_in[0];   // (N,3)
    const float* u_c      = (const float*)d_in[1];   // (1,)
    const float* theta_c  = (const float*)d_in[2];   // (1,)
    const void*  conn     =                d_in[3];  // (E,2) int32 or int64
    const float* L        = (const float*)d_in[4];   // (E,)
    const float* E        = (const float*)d_in[5];
    const float* A        = (const float*)d_in[6];
    const float* I22      = (const float*)d_in[7];
    const float* dirs     = (const float*)d_in[8];   // (E,3)
    const float* F_ext    = (const float*)d_in[9];   // (N,3)
    const int*   bc_disp  = (const int*)  d_in[10];  // (N,1)
    const int*   bc_rot   = (const int*)  d_in[11];  // (N,1)
    float*       out      = (float*)d_out;

    int n_nodes = in_sizes[0] / 3;
    int n_elem  = in_sizes[4];

    const int T = 256;
    detect_conn_kernel<<<1, 256>>>((const unsigned int*)conn, 2 * n_elem);
    prep_kernel<<<(n_nodes + T - 1) / T, T>>>(pred_raw, u_c, theta_c, n_nodes);
    elem_kernel<<<(n_elem + T - 1) / T, T>>>(conn, L, E, A, I22, dirs, n_elem, n_nodes);
    {
        int threads_needed = (n_nodes + 1) / 2;
        reduce_kernel<<<(threads_needed + T - 1) / T, T>>>(F_ext, bc_disp, bc_rot, n_nodes);
    }
    finalize_kernel<<<1, 1>>>(out);
}

// round 4
// speedup vs baseline: 1.8271x; 1.0339x over previous
#include <cuda_runtime.h>
#include <cuda_bf16.h>

// Problem sizes (fixed by the dataset): 1,000,000 nodes, 2,000,000 elements.
#define MAX_NODES 1000000

// Scratch (device globals; allocation-free). Node arrays padded to 4 floats
// so gathers are single LDG.128 and scatters are single red.global.add.v4.f32.
__device__ float  g_uphys4[4 * MAX_NODES];
__device__ float  g_fint4 [4 * MAX_NODES];
__device__ double g_sums[2];     // [0] = sum(R_free^2), [1] = sum(F_free^2)
__device__ int    g_conn_is64;   // 1 if connectivity is int64, 0 if int32

__device__ __forceinline__ void red_add_v4(float* addr, float x, float y, float z, float w)
{
    asm volatile("red.global.add.v4.f32 [%0], {%1, %2, %3, %4};"
                 :: "l"(addr), "f"(x), "f"(y), "f"(z), "f"(w) : "memory");
}

// -------- Kernel 1: dtype probe (block 0) + u_phys4 scale + F_int4 zero -----
// Probe: int64 little-endian with indices < 1e6 => every odd 32-bit word is 0.
//        int32 => odd words are random node indices (virtually all nonzero).
__global__ void prep_kernel(const float* __restrict__ pred_raw,
                            const float* __restrict__ u_c,
                            const float* __restrict__ theta_c,
                            const unsigned int* __restrict__ conn_w,
                            int conn_words,
                            int n_nodes)
{
    if (blockIdx.x == 0) {
        __shared__ unsigned int acc;
        if (threadIdx.x == 0) { acc = 0u; g_sums[0] = 0.0; g_sums[1] = 0.0; }
        __syncthreads();
        unsigned int v = 0u;
        int lim = conn_words < 8192 ? conn_words : 8192;
        for (int i = 2 * threadIdx.x + 1; i < lim; i += 2 * blockDim.x)
            v |= conn_w[i];
        atomicOr(&acc, v);
        __syncthreads();
        if (threadIdx.x == 0) g_conn_is64 = (acc == 0u) ? 1 : 0;
    }
    float uc = u_c[0];
    float tc = theta_c[0];
    int i = blockIdx.x * blockDim.x + threadIdx.x;
    if (i >= n_nodes) return;
    float px = pred_raw[3 * i + 0];
    float py = pred_raw[3 * i + 1];
    float pz = pred_raw[3 * i + 2];
    reinterpret_cast<float4*>(g_uphys4)[i] = make_float4(px * uc, py * uc, pz * tc, 0.0f);
    reinterpret_cast<float4*>(g_fint4 )[i] = make_float4(0.0f, 0.0f, 0.0f, 0.0f);
}

// -------- Kernel 2: element forces, 2 elements per thread -------------------
__global__ void elem_kernel(const void* __restrict__ conn_raw,
                            const float* __restrict__ L,
                            const float* __restrict__ E,
                            const float* __restrict__ A,
                            const float* __restrict__ I22,
                            const float* __restrict__ dirs,       // (E,3)
                            int n_elem, int n_nodes)
{
    int p  = blockIdx.x * blockDim.x + threadIdx.x;   // pair index
    int e0 = 2 * p;
    if (e0 >= n_elem) return;
    bool has1 = (e0 + 1) < n_elem;

    // ---- indices (both elements) ----
    long long nA0, nB0, nA1 = 0, nB1 = 0;
    if (g_conn_is64) {
        longlong2 c0 = reinterpret_cast<const longlong2*>((const long long*)conn_raw)[e0];
        nA0 = c0.x; nB0 = c0.y;
        if (has1) {
            longlong2 c1 = reinterpret_cast<const longlong2*>((const long long*)conn_raw)[e0 + 1];
            nA1 = c1.x; nB1 = c1.y;
        }
    } else {
        if (has1) {
            int4 cc = reinterpret_cast<const int4*>((const int*)conn_raw)[p];
            nA0 = cc.x; nB0 = cc.y; nA1 = cc.z; nB1 = cc.w;
        } else {
            int2 cc = reinterpret_cast<const int2*>((const int*)conn_raw)[e0];
            nA0 = cc.x; nB0 = cc.y;
        }
    }
    if ((unsigned long long)nA0 >= (unsigned long long)n_nodes) nA0 = 0;
    if ((unsigned long long)nB0 >= (unsigned long long)n_nodes) nB0 = 0;
    if ((unsigned long long)nA1 >= (unsigned long long)n_nodes) nA1 = 0;
    if ((unsigned long long)nB1 >= (unsigned long long)n_nodes) nB1 = 0;

    // ---- issue all 4 random gathers up front (max MLP) ----
    float4 uA0 = reinterpret_cast<const float4*>(g_uphys4)[nA0];
    float4 uB0 = reinterpret_cast<const float4*>(g_uphys4)[nB0];
    float4 uA1 = reinterpret_cast<const float4*>(g_uphys4)[has1 ? nA1 : nA0];
    float4 uB1 = reinterpret_cast<const float4*>(g_uphys4)[has1 ? nB1 : nB0];

    // ---- streamed properties (vector loads for the paired case) ----
    float l0, l1 = 1.0f, Ee0, Ee1 = 0.0f, A0, A1v = 0.0f, I0, I1 = 0.0f;
    float c0, s0, c1 = 1.0f, s1 = 0.0f;
    if (has1) {
        float2 lv = reinterpret_cast<const float2*>(L  )[p];
        float2 ev = reinterpret_cast<const float2*>(E  )[p];
        float2 av = reinterpret_cast<const float2*>(A  )[p];
        float2 iv = reinterpret_cast<const float2*>(I22)[p];
        l0 = lv.x; l1 = lv.y; Ee0 = ev.x; Ee1 = ev.y;
        A0 = av.x; A1v = av.y; I0 = iv.x; I1 = iv.y;
        // dirs for elems e0,e0+1: floats [6p .. 6p+5]; 8B-aligned float2 loads
        const float2* d2 = reinterpret_cast<const float2*>(dirs + 6 * p);
        float2 da = d2[0];           // (c0, dirs[3e0+1])
        float2 db = d2[1];           // (s0, c1)
        float2 dc = d2[2];           // (dirs[3e1+1], s1)
        c0 = da.x; s0 = db.x; c1 = db.y; s1 = dc.y;
    } else {
        l0 = L[e0]; Ee0 = E[e0]; A0 = A[e0]; I0 = I22[e0];
        c0 = dirs[3 * e0 + 0]; s0 = dirs[3 * e0 + 2];
    }

    // ---- element 0 ----
    {
        float inv_l = 1.0f / l0;
        float ea_l  = Ee0 * A0 * inv_l;
        float ei_l  = Ee0 * I0 * inv_l;
        float ei_l2 = ei_l * inv_l;
        float ei_l3 = ei_l2 * inv_l;

        float d0 =  c0 * uA0.x + s0 * uA0.y;
        float d1 = -s0 * uA0.x + c0 * uA0.y;
        float d2v = -uA0.z;
        float d3 =  c0 * uB0.x + s0 * uB0.y;
        float d4 = -s0 * uB0.x + c0 * uB0.y;
        float d5 = -uB0.z;

        float du = d0 - d3;
        float dw = d1 - d4;
        float f0 = ea_l * du;
        float f1 = 12.0f * ei_l3 * dw + 6.0f * ei_l2 * (d2v + d5);
        float f2 =  6.0f * ei_l2 * dw + ei_l * (4.0f * d2v + 2.0f * d5);
        float f5 =  6.0f * ei_l2 * dw + ei_l * (2.0f * d2v + 4.0f * d5);

        float gAx = c0 * f0 - s0 * f1;
        float gAy = s0 * f0 + c0 * f1;

        red_add_v4(&g_fint4[4 * nA0],  gAx,  gAy, -f2, 0.0f);
        red_add_v4(&g_fint4[4 * nB0], -gAx, -gAy, -f5, 0.0f);
    }

    // ---- element 1 ----
    if (has1) {
        float inv_l = 1.0f / l1;
        float ea_l  = Ee1 * A1v * inv_l;
        float ei_l  = Ee1 * I1 * inv_l;
        float ei_l2 = ei_l * inv_l;
        float ei_l3 = ei_l2 * inv_l;

        float d0 =  c1 * uA1.x + s1 * uA1.y;
        float d1 = -s1 * uA1.x + c1 * uA1.y;
        float d2v = -uA1.z;
        float d3 =  c1 * uB1.x + s1 * uB1.y;
        float d4 = -s1 * uB1.x + c1 * uB1.y;
        float d5 = -uB1.z;

        float du = d0 - d3;
        float dw = d1 - d4;
        float f0 = ea_l * du;
        float f1 = 12.0f * ei_l3 * dw + 6.0f * ei_l2 * (d2v + d5);
        float f2 =  6.0f * ei_l2 * dw + ei_l * (4.0f * d2v + 2.0f * d5);
        float f5 =  6.0f * ei_l2 * dw + ei_l * (2.0f * d2v + 4.0f * d5);

        float gAx = c1 * f0 - s1 * f1;
        float gAy = s1 * f0 + c1 * f1;

        red_add_v4(&g_fint4[4 * nA1],  gAx,  gAy, -f2, 0.0f);
        red_add_v4(&g_fint4[4 * nB1], -gAx, -gAy, -f5, 0.0f);
    }
}

// -------- Kernel 3: masked residual sums, 4 nodes per thread ----------------
__global__ void reduce_kernel(const float* __restrict__ F_ext,
                              const int*   __restrict__ bc_disp,
                              const int*   __restrict__ bc_rot,
                              int n_nodes)
{
    float sRf = 0.0f, sFf = 0.0f;
    int q  = blockIdx.x * blockDim.x + threadIdx.x;   // quad index
    int i0 = 4 * q;

    if (i0 + 3 < n_nodes) {
        // all loads independent: 4x fint4 + 3x F_ext + 1x bcd + 1x bcr
        const float4* fi4 = reinterpret_cast<const float4*>(g_fint4);
        float4 f0 = fi4[i0 + 0];
        float4 f1 = fi4[i0 + 1];
        float4 f2 = fi4[i0 + 2];
        float4 f3 = fi4[i0 + 3];
        const float4* fe4 = reinterpret_cast<const float4*>(F_ext + 3 * i0);
        float4 e0 = fe4[0];   // n0.x n0.y n0.z n1.x
        float4 e1 = fe4[1];   // n1.y n1.z n2.x n2.y
        float4 e2 = fe4[2];   // n2.z n3.x n3.y n3.z
        int4 bd = reinterpret_cast<const int4*>(bc_disp)[q];
        int4 br = reinterpret_cast<const int4*>(bc_rot )[q];

        float fd0 = 1.0f - (float)bd.x, fr0 = 1.0f - (float)br.x;
        float fd1 = 1.0f - (float)bd.y, fr1 = 1.0f - (float)br.y;
        float fd2 = 1.0f - (float)bd.z, fr2 = 1.0f - (float)br.z;
        float fd3 = 1.0f - (float)bd.w, fr3 = 1.0f - (float)br.w;

        float rx, ry, rz, gx, gy, gz;
        // node 0
        rx = (f0.x - e0.x) * fd0; ry = (f0.y - e0.y) * fd0; rz = (f0.z - e0.z) * fr0;
        gx = e0.x * fd0; gy = e0.y * fd0; gz = e0.z * fr0;
        sRf += rx*rx + ry*ry + rz*rz;  sFf += gx*gx + gy*gy + gz*gz;
        // node 1
        rx = (f1.x - e0.w) * fd1; ry = (f1.y - e1.x) * fd1; rz = (f1.z - e1.y) * fr1;
        gx = e0.w * fd1; gy = e1.x * fd1; gz = e1.y * fr1;
        sRf += rx*rx + ry*ry + rz*rz;  sFf += gx*gx + gy*gy + gz*gz;
        // node 2
        rx = (f2.x - e1.z) * fd2; ry = (f2.y - e1.w) * fd2; rz = (f2.z - e2.x) * fr2;
        gx = e1.z * fd2; gy = e1.w * fd2; gz = e2.x * fr2;
        sRf += rx*rx + ry*ry + rz*rz;  sFf += gx*gx + gy*gy + gz*gz;
        // node 3
        rx = (f3.x - e2.y) * fd3; ry = (f3.y - e2.z) * fd3; rz = (f3.z - e2.w) * fr3;
        gx = e2.y * fd3; gy = e2.z * fd3; gz = e2.w * fr3;
        sRf += rx*rx + ry*ry + rz*rz;  sFf += gx*gx + gy*gy + gz*gz;
    } else {
        for (int i = i0; i < n_nodes; i++) {
            float4 fi = reinterpret_cast<const float4*>(g_fint4)[i];
            float fd = 1.0f - (float)bc_disp[i];
            float fr = 1.0f - (float)bc_rot[i];
            float fx = F_ext[3 * i + 0];
            float fy = F_ext[3 * i + 1];
            float fz = F_ext[3 * i + 2];
            float rx = (fi.x - fx) * fd;
            float ry = (fi.y - fy) * fd;
            float rz = (fi.z - fz) * fr;
            float gx = fx * fd, gy = fy * fd, gz = fz * fr;
            sRf += rx*rx + ry*ry + rz*rz;
            sFf += gx*gx + gy*gy + gz*gz;
        }
    }

    double sR = (double)sRf;
    double sF = (double)sFf;
    for (int off = 16; off > 0; off >>= 1) {
        sR += __shfl_down_sync(0xFFFFFFFFu, sR, off);
        sF += __shfl_down_sync(0xFFFFFFFFu, sF, off);
    }
    __shared__ double shR[8], shF[8];
    int lane = threadIdx.x & 31;
    int wid  = threadIdx.x >> 5;
    if (lane == 0) { shR[wid] = sR; shF[wid] = sF; }
    __syncthreads();
    if (wid == 0) {
        int nw = (blockDim.x + 31) >> 5;
        sR = (lane < nw) ? shR[lane] : 0.0;
        sF = (lane < nw) ? shF[lane] : 0.0;
        for (int off = 4; off > 0; off >>= 1) {
            sR += __shfl_down_sync(0xFFFFFFFFu, sR, off);
            sF += __shfl_down_sync(0xFFFFFFFFu, sF, off);
        }
        if (lane == 0) {
            atomicAdd(&g_sums[0], sR);
            atomicAdd(&g_sums[1], sF);
        }
    }
}

// -------- Kernel 4: final division ------------------------------------------
__global__ void finalize_kernel(float* __restrict__ out)
{
    double denom = g_sums[1];
    if (denom < 1e-30) denom = 1e-30;
    out[0] = (float)(g_sums[0] / denom);
}

extern "C" void kernel_launch(void* const* d_in, const int* in_sizes, int n_in,
                              void* d_out, int out_size)
{
    const float* pred_raw = (const float*)d_in[0];   // (N,3)
    const float* u_c      = (const float*)d_in[1];   // (1,)
    const float* theta_c  = (const float*)d_in[2];   // (1,)
    const void*  conn     =                d_in[3];  // (E,2) int32 or int64
    const float* L        = (const float*)d_in[4];   // (E,)
    const float* E        = (const float*)d_in[5];
    const float* A        = (const float*)d_in[6];
    const float* I22      = (const float*)d_in[7];
    const float* dirs     = (const float*)d_in[8];   // (E,3)
    const float* F_ext    = (const float*)d_in[9];   // (N,3)
    const int*   bc_disp  = (const int*)  d_in[10];  // (N,1)
    const int*   bc_rot   = (const int*)  d_in[11];  // (N,1)
    float*       out      = (float*)d_out;

    int n_nodes = in_sizes[0] / 3;
    int n_elem  = in_sizes[4];

    const int T = 256;
    prep_kernel<<<(n_nodes + T - 1) / T, T>>>(pred_raw, u_c, theta_c,
                                              (const unsigned int*)conn,
                                              2 * n_elem, n_nodes);
    {
        int n_pairs = (n_elem + 1) / 2;
        elem_kernel<<<(n_pairs + T - 1) / T, T>>>(conn, L, E, A, I22, dirs,
                                                  n_elem, n_nodes);
    }
    {
        int n_quads = (n_nodes + 3) / 4;
        reduce_kernel<<<(n_quads + T - 1) / T, T>>>(F_ext, bc_disp, bc_rot, n_nodes);
    }
    finalize_kernel<<<1, 1>>>(out);
}